// round 4
// baseline (speedup 1.0000x reference)
#include <cuda_runtime.h>

// DotProductCostVolume: out[b,d,h,w] = (1/C) * sum_c left[b,c,h,w]*right[b,c,h,w-d], 0 if w<d
// B=4, C=32, H=256, W=512, D=64, fp32.
//
// CTA = (b, h, 256-wide w-tile). Stage L[32c x 256w] (32KB) and R[32c x 320w]
// (40KB, 64-col halo zero-filled for w<0 -> the w<d masking is automatic).
// 16B-chunk XOR swizzle keeps every inner-loop LDS.128 bank-conflict-free.
// Each thread computes an 8w x 16d register tile: per channel, 2+6 LDS.128
// (32 words = 128B/thread) feed 128 FFMAs -> crossbar and FMA pipe co-limiting.

#define Bn 4
#define Cn 32
#define Hn 256
#define Wn 512
#define Dn 64
#define TW 256           // output w-columns per CTA
#define RW 320           // TW + 64 halo columns of right
#define NT 128           // threads per CTA

#define LCH (TW/4)       // 64 float4 chunks per L row
#define RCH (RW/4)       // 80 float4 chunks per R row

// 16B-chunk XOR swizzle (row-local chunk index q); injective, stays in range.
__device__ __forceinline__ int swc(int q) { return q ^ ((q >> 3) & 7); }

__global__ __launch_bounds__(NT, 2)
void cost_volume_kernel(const float* __restrict__ left,
                        const float* __restrict__ right,
                        float* __restrict__ out)
{
    __shared__ float4 Ls4[Cn * LCH];   // 32 KB
    __shared__ float4 Rs4[Cn * RCH];   // 40 KB

    const int tile = blockIdx.x;    // 0..1
    const int h    = blockIdx.y;    // 0..255
    const int b    = blockIdx.z;    // 0..3
    const int w0   = tile * TW;
    const int tid  = threadIdx.x;

    const float* lbase = left  + ((long)(b * Cn) * Hn + h) * Wn;
    const float* rbase = right + ((long)(b * Cn) * Hn + h) * Wn;

    // ---- Stage left tile: chunk q of row c holds words [4q,4q+4) at w0+4q ----
    #pragma unroll 4
    for (int t = tid; t < Cn * LCH; t += NT) {
        int c = t >> 6;             // / 64
        int q = t & (LCH - 1);
        float4 v = *reinterpret_cast<const float4*>(lbase + (long)c * Hn * Wn + w0 + 4 * q);
        Ls4[c * LCH + swc(q)] = v;
    }

    // ---- Stage right tile with halo: chunk q covers global w = w0-64+4q ----
    #pragma unroll 4
    for (int t = tid; t < Cn * RCH; t += NT) {
        int c  = t / RCH;
        int q  = t - c * RCH;
        int gw = w0 - 64 + 4 * q;   // chunk entirely <0 or entirely >=0
        float4 v;
        if (gw >= 0)
            v = *reinterpret_cast<const float4*>(rbase + (long)c * Hn * Wn + gw);
        else
            v = make_float4(0.f, 0.f, 0.f, 0.f);
        Rs4[c * RCH + swc(q)] = v;
    }
    __syncthreads();

    // ---- Per-thread 8w x 16d register tile ----
    const int wg = tid & 31;   // w-group: w0 + 8wg .. +7
    const int dg = tid >> 5;   // d-group: 16dg .. +15

    // L words: 8wg..8wg+7 -> chunks 2wg, 2wg+1
    const float4* La = &Ls4[swc(2 * wg)];
    const float4* Lb = &Ls4[swc(2 * wg + 1)];

    // R words needed: rv[n] = word kb-1+n, n in [1,24), where
    // kb = 8wg - 16dg + 49 (odd). Aligned chunk base q0 = (kb-1)/4 = 2wg-4dg+12,
    // q0 in [0, 74]; 6 chunks cover words 4q0 .. 4q0+23 = kb-1 .. kb+22.
    const int q0 = 2 * wg - 4 * dg + 12;
    const float4* R0 = &Rs4[swc(q0 + 0)];
    const float4* R1 = &Rs4[swc(q0 + 1)];
    const float4* R2 = &Rs4[swc(q0 + 2)];
    const float4* R3 = &Rs4[swc(q0 + 3)];
    const float4* R4 = &Rs4[swc(q0 + 4)];
    const float4* R5 = &Rs4[swc(q0 + 5)];

    float acc[8][16];
    #pragma unroll
    for (int i = 0; i < 8; i++)
        #pragma unroll
        for (int j = 0; j < 16; j++)
            acc[i][j] = 0.0f;

    #pragma unroll 4
    for (int c = 0; c < Cn; c++) {
        float4 la = La[c * LCH];
        float4 lb = Lb[c * LCH];
        float4 r0 = R0[c * RCH];
        float4 r1 = R1[c * RCH];
        float4 r2 = R2[c * RCH];
        float4 r3 = R3[c * RCH];
        float4 r4 = R4[c * RCH];
        float4 r5 = R5[c * RCH];

        float l[8]   = { la.x, la.y, la.z, la.w, lb.x, lb.y, lb.z, lb.w };
        float rv[24] = { r0.x, r0.y, r0.z, r0.w,  r1.x, r1.y, r1.z, r1.w,
                         r2.x, r2.y, r2.z, r2.w,  r3.x, r3.y, r3.z, r3.w,
                         r4.x, r4.y, r4.z, r4.w,  r5.x, r5.y, r5.z, r5.w };

        // word(w=8wg+i, d=16dg+j) = 64 + 8wg + i - 16dg - j = kb + 15 + i - j
        // rv index n = (kb+15+i-j) - (kb-1) = 16 + i - j, in [1, 23]
        #pragma unroll
        for (int i = 0; i < 8; i++)
            #pragma unroll
            for (int j = 0; j < 16; j++)
                acc[i][j] += l[i] * rv[16 + i - j];
    }

    // ---- Epilogue: scale by 1/C, vectorized stores ----
    const float sc = 1.0f / (float)Cn;
    float* ob = out + ((long)(b * Dn) * Hn + h) * Wn + w0 + wg * 8;
    #pragma unroll
    for (int j = 0; j < 16; j++) {
        int d = dg * 16 + j;
        float4 v0 = make_float4(acc[0][j] * sc, acc[1][j] * sc,
                                acc[2][j] * sc, acc[3][j] * sc);
        float4 v1 = make_float4(acc[4][j] * sc, acc[5][j] * sc,
                                acc[6][j] * sc, acc[7][j] * sc);
        float4* p = reinterpret_cast<float4*>(ob + (long)d * Hn * Wn);
        p[0] = v0;
        p[1] = v1;
    }
}

extern "C" void kernel_launch(void* const* d_in, const int* in_sizes, int n_in,
                              void* d_out, int out_size)
{
    const float* left  = (const float*)d_in[0];
    const float* right = (const float*)d_in[1];
    float* out = (float*)d_out;

    dim3 grid(Wn / TW, Hn, Bn);   // (2, 256, 4) = 2048 CTAs
    cost_volume_kernel<<<grid, NT>>>(left, right, out);
}

// round 5
// speedup vs baseline: 1.1101x; 1.1101x over previous
#include <cuda_runtime.h>

// DotProductCostVolume: out[b,d,h,w] = (1/C) * sum_c left[b,c,h,w]*right[b,c,h,w-d], 0 if w<d
// B=4, C=32, H=256, W=512, D=64, fp32.
//
// R3 geometry (best measured issue config): CTA = (b, h, 128-wide w-tile),
// 128 threads, 4 CTAs/SM. Stage L[32c x 128w] + R[32c x 192w] (halo zero-filled
// so w<d masking is automatic), 16B-chunk XOR swizzle -> conflict-free LDS.128.
// NEW: math uses Blackwell packed fma.rn.f32x2 — accumulators paired along w,
// halving fma-pipe demand and cutting issued instructions per channel.

#define Bn 4
#define Cn 32
#define Hn 256
#define Wn 512
#define Dn 64
#define TW 128           // output w-columns per CTA
#define RW 192           // TW + 64 halo columns of right
#define NT 128           // threads per CTA

#define LCH (TW/4)       // 32 float4 chunks per L row
#define RCH (RW/4)       // 48 float4 chunks per R row

typedef unsigned long long ull;

// 16B-chunk XOR swizzle (row-local chunk index q)
__device__ __forceinline__ int swc(int q) { return q ^ ((q >> 3) & 7); }

__device__ __forceinline__ ull pk(float lo, float hi) {
    ull r;
    asm("mov.b64 %0, {%1, %2};" : "=l"(r) : "f"(lo), "f"(hi));
    return r;
}
__device__ __forceinline__ void fma2(ull& d, ull a, ull b) {
    asm("fma.rn.f32x2 %0, %1, %2, %0;" : "+l"(d) : "l"(a), "l"(b));
}
__device__ __forceinline__ ull mul2(ull a, ull b) {
    ull r;
    asm("mul.rn.f32x2 %0, %1, %2;" : "=l"(r) : "l"(a), "l"(b));
    return r;
}
__device__ __forceinline__ void upk(ull v, float& lo, float& hi) {
    asm("mov.b64 {%0, %1}, %2;" : "=f"(lo), "=f"(hi) : "l"(v));
}

__global__ __launch_bounds__(NT, 4)
void cost_volume_kernel(const float* __restrict__ left,
                        const float* __restrict__ right,
                        float* __restrict__ out)
{
    __shared__ float4 Ls4[Cn * LCH];   // 16 KB
    __shared__ float4 Rs4[Cn * RCH];   // 24 KB

    const int tile = blockIdx.x;    // 0..3
    const int h    = blockIdx.y;    // 0..255
    const int b    = blockIdx.z;    // 0..3
    const int w0   = tile * TW;
    const int tid  = threadIdx.x;

    const float* lbase = left  + ((long)(b * Cn) * Hn + h) * Wn;
    const float* rbase = right + ((long)(b * Cn) * Hn + h) * Wn;

    // ---- Stage left tile ----
    #pragma unroll 4
    for (int t = tid; t < Cn * LCH; t += NT) {
        int c = t >> 5;             // / 32
        int q = t & (LCH - 1);
        float4 v = *reinterpret_cast<const float4*>(lbase + (long)c * Hn * Wn + w0 + 4 * q);
        Ls4[c * LCH + swc(q)] = v;
    }

    // ---- Stage right tile with halo (zero for w<0) ----
    #pragma unroll 4
    for (int t = tid; t < Cn * RCH; t += NT) {
        int c  = t / RCH;
        int q  = t - c * RCH;
        int gw = w0 - 64 + 4 * q;   // chunk entirely <0 or entirely >=0
        float4 v;
        if (gw >= 0)
            v = *reinterpret_cast<const float4*>(rbase + (long)c * Hn * Wn + gw);
        else
            v = make_float4(0.f, 0.f, 0.f, 0.f);
        Rs4[c * RCH + swc(q)] = v;
    }
    __syncthreads();

    // ---- Per-thread 8w x 8d tile, computed as 4 (w-pair) x 8 d f32x2 accs ----
    const int wg = tid & 15;   // w-group: w0 + 8wg .. +7
    const int dg = tid >> 4;   // d-group: 8dg .. +7

    const float4* La = &Ls4[swc(2 * wg)];
    const float4* Lb = &Ls4[swc(2 * wg + 1)];

    // R words rv[n] = word (8wg - 8dg + 56) + n, n in [0,15]; base is 4-aligned.
    const int q0 = 2 * (wg - dg) + 14;           // in [0, 44]
    const float4* R0 = &Rs4[swc(q0 + 0)];
    const float4* R1 = &Rs4[swc(q0 + 1)];
    const float4* R2 = &Rs4[swc(q0 + 2)];
    const float4* R3 = &Rs4[swc(q0 + 3)];

    // acc2[a][j] = ( acc[2a][j] , acc[2a+1][j] )
    ull acc2[4][8];
    #pragma unroll
    for (int a = 0; a < 4; a++)
        #pragma unroll
        for (int j = 0; j < 8; j++)
            acc2[a][j] = 0ull;

    #pragma unroll 8
    for (int c = 0; c < Cn; c++) {
        float4 la = La[c * LCH];
        float4 lb = Lb[c * LCH];
        float4 r0 = R0[c * RCH];
        float4 r1 = R1[c * RCH];
        float4 r2 = R2[c * RCH];
        float4 r3 = R3[c * RCH];

        float rv[16] = { r0.x, r0.y, r0.z, r0.w,  r1.x, r1.y, r1.z, r1.w,
                         r2.x, r2.y, r2.z, r2.w,  r3.x, r3.y, r3.z, r3.w };

        // L pairs (l[2a], l[2a+1])
        ull L2[4] = { pk(la.x, la.y), pk(la.z, la.w),
                      pk(lb.x, lb.y), pk(lb.z, lb.w) };

        // R pairs P[m-1] = (rv[m], rv[m+1]), m in [1,14]
        ull P[14];
        #pragma unroll
        for (int m = 1; m <= 14; m++)
            P[m - 1] = pk(rv[m], rv[m + 1]);

        // acc[i][j] += l[i] * rv[8+i-j]; pair i=2a,2a+1 -> m = 8+2a-j in [1,14]
        #pragma unroll
        for (int a = 0; a < 4; a++)
            #pragma unroll
            for (int j = 0; j < 8; j++)
                fma2(acc2[a][j], L2[a], P[8 + 2 * a - j - 1]);
    }

    // ---- Epilogue: scale by 1/C (packed), unpack, vectorized stores ----
    const float sc = 1.0f / (float)Cn;
    const ull SC = pk(sc, sc);
    float* ob = out + ((long)(b * Dn) * Hn + h) * Wn + w0 + wg * 8;
    #pragma unroll
    for (int j = 0; j < 8; j++) {
        int d = dg * 8 + j;
        float a0, a1, a2, a3, a4, a5, a6, a7;
        upk(mul2(acc2[0][j], SC), a0, a1);
        upk(mul2(acc2[1][j], SC), a2, a3);
        upk(mul2(acc2[2][j], SC), a4, a5);
        upk(mul2(acc2[3][j], SC), a6, a7);
        float4* p = reinterpret_cast<float4*>(ob + (long)d * Hn * Wn);
        p[0] = make_float4(a0, a1, a2, a3);
        p[1] = make_float4(a4, a5, a6, a7);
    }
}

extern "C" void kernel_launch(void* const* d_in, const int* in_sizes, int n_in,
                              void* d_out, int out_size)
{
    const float* left  = (const float*)d_in[0];
    const float* right = (const float*)d_in[1];
    float* out = (float*)d_out;

    dim3 grid(Wn / TW, Hn, Bn);   // (4, 256, 4) = 4096 CTAs
    cost_volume_kernel<<<grid, NT>>>(left, right, out);
}